// round 4
// baseline (speedup 1.0000x reference)
#include <cuda_runtime.h>
#include <math.h>
#include <cstdint>

// Problem dims
#define B_SZ 512
#define T_IN 1125
#define E_SZ 5
#define C_SZ 40
#define L_SZ 216
#define G_SZ 40
#define H_SZ 10
#define KK   125
#define XG_STRIDE (B_SZ*G_SZ)

// ---- persistent scratch ----
__device__ __align__(16) float d_Wcomb[KK*G_SZ];     // [kk][g]
__device__ __align__(16) float d_bg[G_SZ];
__device__ __align__(16) float d_xg[L_SZ*B_SZ*G_SZ]; // [t][b][g]

__device__ __forceinline__ float tanh_a(float x) {
    float r; asm("tanh.approx.f32 %0, %1;" : "=f"(r) : "f"(x)); return r;
}

// ============================================================
// Kernel 0: fold conv_time, conv_spat, BN, avgpool, w_ih, biases
// into Wcomb[125][40] + bg[40]. 40 CTAs, one gate each.
// ============================================================
__global__ void __launch_bounds__(256) prep_kernel(
        const float* __restrict__ wt,     // [40][25]
        const float* __restrict__ tb,     // [40]
        const float* __restrict__ ws,     // [40][40][5]
        const float* __restrict__ gamma,
        const float* __restrict__ beta,
        const float* __restrict__ mean,
        const float* __restrict__ var,
        const float* __restrict__ wih,    // [40][40]
        const float* __restrict__ bih,
        const float* __restrict__ bhh)
{
    __shared__ float s_ws[C_SZ*C_SZ*E_SZ];   // 8000
    __shared__ float s_wt[C_SZ*25];
    __shared__ float s_wr[C_SZ], s_wsc[C_SZ], s_shift[C_SZ], s_tb[C_SZ];
    __shared__ float A_s[C_SZ*E_SZ];         // [cp][e]
    __shared__ float red[256];
    int t = threadIdx.x;
    int g = blockIdx.x;

    for (int i = t; i < C_SZ*C_SZ*E_SZ; i += 256) s_ws[i] = ws[i];
    for (int i = t; i < C_SZ*25;        i += 256) s_wt[i] = wt[i];
    if (t < C_SZ) {
        float sc = gamma[t] * rsqrtf(var[t] + 1e-5f);
        float wr = wih[g*C_SZ + t];
        s_wr[t]  = wr;
        s_wsc[t] = wr * sc;
        s_shift[t] = beta[t] - mean[t]*sc;
        s_tb[t] = tb[t];
    }
    __syncthreads();

    // A[cp][e] = sum_c wih[g,c]*scale[c]*ws[c,cp,e]
    if (t < C_SZ*E_SZ) {
        int cp = t / E_SZ, e = t % E_SZ;
        float s = 0.f;
        #pragma unroll 8
        for (int c = 0; c < C_SZ; c++) s += s_wsc[c] * s_ws[c*200 + cp*E_SZ + e];
        A_s[t] = s;
    }
    __syncthreads();

    // Wcomb[kk][g], kk = 5k+e
    if (t < KK) {
        int k = t / E_SZ, e = t % E_SZ;
        float s = 0.f;
        #pragma unroll 8
        for (int cp = 0; cp < C_SZ; cp++) s += A_s[cp*E_SZ + e] * s_wt[cp*25 + k];
        d_Wcomb[t*G_SZ + g] = s * (1.0f/25.0f);
    }

    // bg[g]
    float part = 0.f;
    for (int idx = t; idx < 1600; idx += 256) {
        int c = idx / C_SZ, cp = idx % C_SZ;
        const float* w5 = &s_ws[c*200 + cp*E_SZ];
        float s5 = w5[0]+w5[1]+w5[2]+w5[3]+w5[4];
        part += s_wsc[c] * s_tb[cp] * s5;
    }
    if (t < C_SZ) part += s_wr[t] * s_shift[t];
    red[t] = part;
    __syncthreads();
    for (int off = 128; off > 0; off >>= 1) {
        if (t < off) red[t] += red[t + off];
        __syncthreads();
    }
    if (t == 0) d_bg[g] = bih[g] + bhh[g] + red[0];
}

// ============================================================
// Kernel 1: conv/pool/GEMM with transposed box-sum buffer.
// grid (2 halves, 512 b), 288 threads. Inner loop per kk:
// 1 LDS.128 (w, 4 gates) + 1 LDS.128 (x, 4 p) + 16 FFMA.
// ============================================================
#define CONV_THREADS 288
// dynamic smem layout (floats)
#define OFF_WS   0                 // 5000
#define OFF_BG   5000              // 40 (pad to 5040)
#define OFF_BSUM 5040              // 2800
#define OFF_BST  7840              // 13500  (x slab 2920 aliased here)
#define CONV_SMEM_FLOATS (7840 + 13500)
#define CONV_SMEM_BYTES  (CONV_SMEM_FLOATS*4)   // 85360

__global__ void __launch_bounds__(CONV_THREADS) conv_kernel(const float* __restrict__ x)
{
    extern __shared__ float sm[];
    float* Ws   = sm + OFF_WS;
    float* bg_s = sm + OFF_BG;
    float* Bsum = sm + OFF_BSUM;
    float* Bst  = sm + OFF_BST;
    float* xs   = Bst;                 // alias: x slab dead before transpose

    int tid  = threadIdx.x;
    int half = blockIdx.x;
    int b    = blockIdx.y;

    const float* xb = x + (size_t)b*(T_IN*E_SZ) + half*2700;
    for (int i = tid; i < 2920; i += CONV_THREADS) xs[i] = xb[i];
    for (int i = tid; i < KK*G_SZ; i += CONV_THREADS) Ws[i] = d_Wcomb[i];
    if (tid < G_SZ) bg_s[tid] = d_bg[tid];
    __syncthreads();

    // Bsum[t*5+e] = sum_{j<25} xs[(t+j)*5+e], t in [0,560)
    {
        int e = tid % 5, seg = tid / 5;      // seg 0..57
        int t0 = seg*10;
        if (t0 < 560) {
            int t1 = min(t0+10, 560);
            float s = 0.f;
            #pragma unroll
            for (int j = 0; j < 25; j++) s += xs[(t0+j)*5 + e];
            Bsum[t0*5+e] = s;
            for (int tt = t0+1; tt < t1; tt++) {
                s += xs[(tt+24)*5+e] - xs[(tt-1)*5+e];
                Bsum[tt*5+e] = s;
            }
        }
    }
    __syncthreads();

    // transpose: Bst[kk*108 + pl] = Bsum[(5*pl + k)*5 + e],  kk = 5k+e
    for (int idx = tid; idx < KK*108; idx += CONV_THREADS) {
        int kk = idx / 108;
        int pl = idx - kk*108;
        int k  = kk / 5;
        int e  = kk - k*5;
        Bst[idx] = Bsum[(5*pl + k)*5 + e];
    }
    __syncthreads();

    if (tid < 270) {
        int gq = tid / 27;            // 0..9  -> gates 4gq..4gq+3
        int pq = tid - gq*27;         // 0..26 -> p 4pq..4pq+3
        const float4* wp = (const float4*)Ws  + gq;    // wp[kk*10]
        const float4* xq = (const float4*)Bst + pq;    // xq[kk*27]

        float4 bg4 = ((const float4*)bg_s)[gq];
        float a00=bg4.x,a01=bg4.x,a02=bg4.x,a03=bg4.x;
        float a10=bg4.y,a11=bg4.y,a12=bg4.y,a13=bg4.y;
        float a20=bg4.z,a21=bg4.z,a22=bg4.z,a23=bg4.z;
        float a30=bg4.w,a31=bg4.w,a32=bg4.w,a33=bg4.w;

        #pragma unroll 5
        for (int kk = 0; kk < KK; kk++) {
            float4 w  = wp[kk*10];
            float4 xv = xq[kk*27];
            a00 = fmaf(w.x, xv.x, a00); a01 = fmaf(w.x, xv.y, a01);
            a02 = fmaf(w.x, xv.z, a02); a03 = fmaf(w.x, xv.w, a03);
            a10 = fmaf(w.y, xv.x, a10); a11 = fmaf(w.y, xv.y, a11);
            a12 = fmaf(w.y, xv.z, a12); a13 = fmaf(w.y, xv.w, a13);
            a20 = fmaf(w.z, xv.x, a20); a21 = fmaf(w.z, xv.y, a21);
            a22 = fmaf(w.z, xv.z, a22); a23 = fmaf(w.z, xv.w, a23);
            a30 = fmaf(w.w, xv.x, a30); a31 = fmaf(w.w, xv.y, a31);
            a32 = fmaf(w.w, xv.z, a32); a33 = fmaf(w.w, xv.w, a33);
        }

        int p0 = half*108 + 4*pq;
        float* dst = d_xg + (size_t)p0*XG_STRIDE + b*G_SZ + 4*gq;
        *(float4*)(dst               ) = make_float4(a00, a10, a20, a30);
        *(float4*)(dst +   XG_STRIDE ) = make_float4(a01, a11, a21, a31);
        *(float4*)(dst + 2*XG_STRIDE ) = make_float4(a02, a12, a22, a32);
        *(float4*)(dst + 3*XG_STRIDE ) = make_float4(a03, a13, a23, a33);
    }
}

// ============================================================
// Kernel 2: LSTM scan (216 steps) + final FC.
// ============================================================
__global__ void __launch_bounds__(128) lstm_kernel(const float* __restrict__ whh,  // [40][10]
                                                   const float* __restrict__ fcw,  // [2][10]
                                                   const float* __restrict__ fcb,
                                                   float* __restrict__ out)
{
    int warp = threadIdx.x >> 5;
    int lid  = threadIdx.x & 31;
    int b    = blockIdx.x*4 + warp;

    int r = min(lid, 19);
    float wa[H_SZ], wb[H_SZ];
    #pragma unroll
    for (int j = 0; j < H_SZ; j++) {
        wa[j] = whh[r*H_SZ + j];
        wb[j] = whh[(r+20)*H_SZ + j];
    }
    const float sc2 = (lid < 10) ? 1.0f : 0.5f;
    const float k1  = (lid < 10) ? 1.0f : 0.5f;
    const float k0  = (lid < 10) ? 0.0f : 0.5f;

    float h[H_SZ];
    #pragma unroll
    for (int j = 0; j < H_SZ; j++) h[j] = 0.f;
    float c = 0.f;

    const float* xp = d_xg + (size_t)b*G_SZ + r;
    float p1 = __ldg(xp);
    float p2 = __ldg(xp + 20);

    for (int t = 0; t < L_SZ; t++) {
        float cur1 = p1, cur2 = p2;
        if (t < L_SZ-1) {
            const float* nx = xp + (size_t)(t+1)*XG_STRIDE;
            p1 = __ldg(nx);
            p2 = __ldg(nx + 20);
        }
        float s1a = cur1, s1b = 0.f, s2a = cur2, s2b = 0.f;
        #pragma unroll
        for (int j = 0; j < 5; j++) {
            s1a = fmaf(wa[j],   h[j],   s1a);
            s1b = fmaf(wa[j+5], h[j+5], s1b);
            s2a = fmaf(wb[j],   h[j],   s2a);
            s2b = fmaf(wb[j+5], h[j+5], s2b);
        }
        float g1 = s1a + s1b;
        float g2 = s2a + s2b;
        float a1 = fmaf(0.5f, tanh_a(0.5f*g1), 0.5f);   // sigmoid: i / f
        float a2 = fmaf(k1,   tanh_a(sc2*g2),  k0);     // tanh g / sigmoid o
        float fv = __shfl_sync(0xffffffffu, a1, lid + 10);
        float ov = __shfl_sync(0xffffffffu, a2, lid + 10);
        c = fmaf(fv, c, a1*a2);
        float hv = ov * tanh_a(c);
        #pragma unroll
        for (int j = 0; j < H_SZ; j++)
            h[j] = __shfl_sync(0xffffffffu, hv, j);
    }

    if (lid < 2) {
        float o = fcb[lid];
        #pragma unroll
        for (int j = 0; j < H_SZ; j++) o = fmaf(fcw[lid*H_SZ + j], h[j], o);
        out[b*2 + lid] = o;
    }
}

// ============================================================
extern "C" void kernel_launch(void* const* d_in, const int* in_sizes, int n_in,
                              void* d_out, int out_size)
{
    const float* x     = (const float*)d_in[0];
    const float* ctw   = (const float*)d_in[1];
    const float* ctb   = (const float*)d_in[2];
    const float* csw   = (const float*)d_in[3];
    const float* gamma = (const float*)d_in[4];
    const float* beta  = (const float*)d_in[5];
    const float* mean  = (const float*)d_in[6];
    const float* var   = (const float*)d_in[7];
    const float* wih   = (const float*)d_in[8];
    const float* whh   = (const float*)d_in[9];
    const float* bih   = (const float*)d_in[10];
    const float* bhh   = (const float*)d_in[11];
    const float* fcw   = (const float*)d_in[12];
    const float* fcb   = (const float*)d_in[13];
    float* out = (float*)d_out;

    cudaFuncSetAttribute(conv_kernel, cudaFuncAttributeMaxDynamicSharedMemorySize, CONV_SMEM_BYTES);

    prep_kernel<<<G_SZ, 256>>>(ctw, ctb, csw, gamma, beta, mean, var, wih, bih, bhh);
    conv_kernel<<<dim3(2, B_SZ), CONV_THREADS, CONV_SMEM_BYTES>>>(x);
    lstm_kernel<<<B_SZ/4, 128>>>(whh, fcw, fcb, out);
}

// round 6
// speedup vs baseline: 1.4295x; 1.4295x over previous
#include <cuda_runtime.h>
#include <math.h>
#include <cstdint>

// Problem dims
#define B_SZ 512
#define T_IN 1125
#define E_SZ 5
#define C_SZ 40
#define L_SZ 216
#define G_SZ 40
#define H_SZ 10
#define KK   125
#define XG_STRIDE (B_SZ*G_SZ)

// ---- persistent scratch ----
__device__ __align__(16) float d_Wcomb[KK*G_SZ];     // [kk][g]
__device__ __align__(16) float d_bg[G_SZ];
__device__ __align__(16) float d_xg[L_SZ*B_SZ*G_SZ]; // [t][b][g]

__device__ __forceinline__ float tanh_a(float x) {
    float r; asm("tanh.approx.f32 %0, %1;" : "=f"(r) : "f"(x)); return r;
}
__device__ __forceinline__ uint32_t smem_u32(const void* p) {
    uint32_t a;
    asm("{ .reg .u64 t; cvta.to.shared.u64 t, %1; cvt.u32.u64 %0, t; }" : "=r"(a) : "l"(p));
    return a;
}

// ============================================================
// Kernel 0: fold conv_time, conv_spat, BN, avgpool, w_ih, biases
// into Wcomb[125][40] + bg[40]. 40 CTAs, one gate each.
// ============================================================
__global__ void __launch_bounds__(256) prep_kernel(
        const float* __restrict__ wt,     // [40][25]
        const float* __restrict__ tb,     // [40]
        const float* __restrict__ ws,     // [40][40][5]
        const float* __restrict__ gamma,
        const float* __restrict__ beta,
        const float* __restrict__ mean,
        const float* __restrict__ var,
        const float* __restrict__ wih,    // [40][40]
        const float* __restrict__ bih,
        const float* __restrict__ bhh)
{
    __shared__ __align__(16) float s_ws[C_SZ*C_SZ*E_SZ];   // 8000
    __shared__ __align__(16) float s_wt[C_SZ*25];
    __shared__ float s_wr[C_SZ], s_wsc[C_SZ], s_shift[C_SZ], s_tb[C_SZ];
    __shared__ float A_s[C_SZ*E_SZ];
    __shared__ float red[8];
    int t = threadIdx.x;
    int g = blockIdx.x;

    for (int i = t; i < 2000; i += 256) ((float4*)s_ws)[i] = ((const float4*)ws)[i];
    for (int i = t; i < 250;  i += 256) ((float4*)s_wt)[i] = ((const float4*)wt)[i];
    if (t < C_SZ) {
        float sc = gamma[t] * rsqrtf(var[t] + 1e-5f);
        float wr = wih[g*C_SZ + t];
        s_wr[t]  = wr;
        s_wsc[t] = wr * sc;
        s_shift[t] = beta[t] - mean[t]*sc;
        s_tb[t] = tb[t];
    }
    __syncthreads();

    // A[cp][e] = sum_c wih[g,c]*scale[c]*ws[c,cp,e]
    if (t < C_SZ*E_SZ) {
        int cp = t / E_SZ, e = t % E_SZ;
        float s = 0.f;
        #pragma unroll 8
        for (int c = 0; c < C_SZ; c++) s += s_wsc[c] * s_ws[c*200 + cp*E_SZ + e];
        A_s[t] = s;
    }
    __syncthreads();

    // Wcomb[kk][g], kk = 5k+e
    if (t < KK) {
        int k = t / E_SZ, e = t % E_SZ;
        float s = 0.f;
        #pragma unroll 8
        for (int cp = 0; cp < C_SZ; cp++) s += A_s[cp*E_SZ + e] * s_wt[cp*25 + k];
        d_Wcomb[t*G_SZ + g] = s * (1.0f/25.0f);
    }

    // bg[g]
    float part = 0.f;
    for (int idx = t; idx < 1600; idx += 256) {
        int c = idx / C_SZ, cp = idx % C_SZ;
        const float* w5 = &s_ws[c*200 + cp*E_SZ];
        float s5 = w5[0]+w5[1]+w5[2]+w5[3]+w5[4];
        part += s_wsc[c] * s_tb[cp] * s5;
    }
    if (t < C_SZ) part += s_wr[t] * s_shift[t];
    #pragma unroll
    for (int o = 16; o > 0; o >>= 1) part += __shfl_xor_sync(0xffffffffu, part, o);
    if ((t & 31) == 0) red[t >> 5] = part;
    __syncthreads();
    if (t == 0) {
        float s = red[0]+red[1]+red[2]+red[3]+red[4]+red[5]+red[6]+red[7];
        d_bg[g] = bih[g] + bhh[g] + s;
    }
}

// ============================================================
// Kernel 1: conv/pool/GEMM, 3 tiles of 72 p, 192 threads.
// Inner loop per kk: LDS.128 w + LDS.128 x + 16 FFMA.
// ============================================================
#define CONV_THREADS 192
#define PTILE 72
// smem floats (NOTE: bg needs 40 floats -> Bsum starts at 5040)
#define OFF_WS   0                 // 5000 floats
#define OFF_BG   5000              // 40 floats (5000..5040)
#define OFF_BSUM 5040              // 1900 used (+4 pad) -> ends 6944
#define OFF_BST  6944              // 9000 = 125*72 (x slab 2020 aliased)
#define CONV_SMEM_FLOATS (6944 + 9000)
#define CONV_SMEM_BYTES  (CONV_SMEM_FLOATS*4)   // 63776

__global__ void __launch_bounds__(CONV_THREADS) conv_kernel(const float* __restrict__ x)
{
    extern __shared__ float sm[];
    float* Ws   = sm + OFF_WS;
    float* bg_s = sm + OFF_BG;
    float* Bsum = sm + OFF_BSUM;
    float* Bst  = sm + OFF_BST;
    float* xs   = Bst;                 // alias: x slab dead before transpose

    int tid  = threadIdx.x;
    int q    = blockIdx.x;             // tile 0..2
    int b    = blockIdx.y;

    const float* xb = x + (size_t)b*(T_IN*E_SZ) + q*(PTILE*5*E_SZ);   // q*1800
    for (int i = tid; i < 2020; i += CONV_THREADS) xs[i] = xb[i];
    for (int i = tid; i < KK*G_SZ; i += CONV_THREADS) Ws[i] = d_Wcomb[i];
    if (tid < G_SZ) bg_s[tid] = d_bg[tid];
    __syncthreads();

    // Bsum[t*5+e] = sum_{j<25} xs[(t+j)*5+e], t in [0,380)
    {
        int e = tid % 5, seg = tid / 5;      // seg 0..38
        int t0 = seg*10;
        if (t0 < 380) {
            int t1 = min(t0+10, 380);
            float s = 0.f;
            #pragma unroll
            for (int j = 0; j < 25; j++) s += xs[(t0+j)*5 + e];
            Bsum[t0*5+e] = s;
            for (int tt = t0+1; tt < t1; tt++) {
                s += xs[(tt+24)*5+e] - xs[(tt-1)*5+e];
                Bsum[tt*5+e] = s;
            }
        }
    }
    __syncthreads();

    // transpose: Bst[kk*72 + pl] = Bsum[(5*pl + k)*5 + e],  kk = 5k+e
    for (int idx = tid; idx < KK*PTILE; idx += CONV_THREADS) {
        int kk = idx / PTILE;
        int pl = idx - kk*PTILE;
        int k  = kk / 5;
        int e  = kk - k*5;
        Bst[idx] = Bsum[(5*pl + k)*5 + e];
    }
    __syncthreads();

    if (tid < 180) {
        int gq = tid / 18;            // 0..9  -> gates 4gq..4gq+3
        int pq = tid - gq*18;         // 0..17 -> p 4pq..4pq+3
        const float4* wp = (const float4*)Ws  + gq;    // wp[kk*10]
        const float4* xq = (const float4*)Bst + pq;    // xq[kk*18]

        float4 bg4 = ((const float4*)bg_s)[gq];
        float a00=bg4.x,a01=bg4.x,a02=bg4.x,a03=bg4.x;
        float a10=bg4.y,a11=bg4.y,a12=bg4.y,a13=bg4.y;
        float a20=bg4.z,a21=bg4.z,a22=bg4.z,a23=bg4.z;
        float a30=bg4.w,a31=bg4.w,a32=bg4.w,a33=bg4.w;

        #pragma unroll 5
        for (int kk = 0; kk < KK; kk++) {
            float4 w  = wp[kk*10];
            float4 xv = xq[kk*18];
            a00 = fmaf(w.x, xv.x, a00); a01 = fmaf(w.x, xv.y, a01);
            a02 = fmaf(w.x, xv.z, a02); a03 = fmaf(w.x, xv.w, a03);
            a10 = fmaf(w.y, xv.x, a10); a11 = fmaf(w.y, xv.y, a11);
            a12 = fmaf(w.y, xv.z, a12); a13 = fmaf(w.y, xv.w, a13);
            a20 = fmaf(w.z, xv.x, a20); a21 = fmaf(w.z, xv.y, a21);
            a22 = fmaf(w.z, xv.z, a22); a23 = fmaf(w.z, xv.w, a23);
            a30 = fmaf(w.w, xv.x, a30); a31 = fmaf(w.w, xv.y, a31);
            a32 = fmaf(w.w, xv.z, a32); a33 = fmaf(w.w, xv.w, a33);
        }

        int p0 = q*PTILE + 4*pq;
        float* dst = d_xg + (size_t)p0*XG_STRIDE + b*G_SZ + 4*gq;
        *(float4*)(dst               ) = make_float4(a00, a10, a20, a30);
        *(float4*)(dst +   XG_STRIDE ) = make_float4(a01, a11, a21, a31);
        *(float4*)(dst + 2*XG_STRIDE ) = make_float4(a02, a12, a22, a32);
        *(float4*)(dst + 3*XG_STRIDE ) = make_float4(a03, a13, a23, a33);
    }
}

// ============================================================
// Kernel 2: LSTM scan + FC. Warp-private xg slice staged to smem
// via cp.async, then register/smem-only scan.
// ============================================================
#define LSTM_WARPS 4
#define XSLICE_FLOATS (L_SZ*G_SZ)            // 8640
#define XSLICE_BYTES  (XSLICE_FLOATS*4)      // 34560
#define LSTM_SMEM_BYTES (LSTM_WARPS*XSLICE_BYTES + 256)  // pad for t+1 overrun

__global__ void __launch_bounds__(32*LSTM_WARPS) lstm_kernel(
        const float* __restrict__ whh,  // [40][10]
        const float* __restrict__ fcw,  // [2][10]
        const float* __restrict__ fcb,
        float* __restrict__ out)
{
    extern __shared__ float xsm[];
    int warp = threadIdx.x >> 5;
    int lid  = threadIdx.x & 31;
    int b    = blockIdx.x*LSTM_WARPS + warp;

    // stage xg[:, b, :] -> smem slice (2160 x 16B cp.async)
    {
        uint32_t dst0 = smem_u32(xsm) + warp*XSLICE_BYTES;
        const char* src0 = (const char*)(d_xg + (size_t)b*G_SZ);
        for (int c = lid; c < 2160; c += 32) {
            int t = c / 10;
            int e = c - t*10;
            uint32_t dst = dst0 + (uint32_t)(t*160 + e*16);
            const void* src = src0 + (size_t)t*(XG_STRIDE*4) + e*16;
            asm volatile("cp.async.ca.shared.global [%0], [%1], 16;" :: "r"(dst), "l"(src));
        }
        asm volatile("cp.async.commit_group;" ::: "memory");
        asm volatile("cp.async.wait_group 0;" ::: "memory");
        __syncwarp();
    }
    const float* xw = xsm + warp*XSLICE_FLOATS;

    int r = min(lid, 19);
    float wa[H_SZ], wb[H_SZ];
    #pragma unroll
    for (int j = 0; j < H_SZ; j++) {
        wa[j] = whh[r*H_SZ + j];
        wb[j] = whh[(r+20)*H_SZ + j];
    }
    const float sc2 = (lid < 10) ? 1.0f : 0.5f;
    const float k1  = (lid < 10) ? 1.0f : 0.5f;
    const float k0  = (lid < 10) ? 0.0f : 0.5f;

    float h[H_SZ];
    #pragma unroll
    for (int j = 0; j < H_SZ; j++) h[j] = 0.f;
    float c = 0.f;

    float cur1 = xw[r], cur2 = xw[20 + r];
    for (int t = 0; t < L_SZ; t++) {
        // prefetch next step from smem (overrun at t=215 lands in pad)
        float n1 = xw[(t+1)*G_SZ + r];
        float n2 = xw[(t+1)*G_SZ + 20 + r];

        float s1a = cur1, s1b = 0.f, s2a = cur2, s2b = 0.f;
        #pragma unroll
        for (int j = 0; j < 5; j++) {
            s1a = fmaf(wa[j],   h[j],   s1a);
            s1b = fmaf(wa[j+5], h[j+5], s1b);
            s2a = fmaf(wb[j],   h[j],   s2a);
            s2b = fmaf(wb[j+5], h[j+5], s2b);
        }
        float g1 = s1a + s1b;
        float g2 = s2a + s2b;
        float a1 = fmaf(0.5f, tanh_a(0.5f*g1), 0.5f);   // sigmoid: i / f
        float a2 = fmaf(k1,   tanh_a(sc2*g2),  k0);     // tanh g / sigmoid o
        float fv = __shfl_sync(0xffffffffu, a1, lid + 10);
        float ov = __shfl_sync(0xffffffffu, a2, lid + 10);
        c = fmaf(fv, c, a1*a2);
        float hv = ov * tanh_a(c);
        #pragma unroll
        for (int j = 0; j < H_SZ; j++)
            h[j] = __shfl_sync(0xffffffffu, hv, j);
        cur1 = n1; cur2 = n2;
    }

    if (lid < 2) {
        float o = fcb[lid];
        #pragma unroll
        for (int j = 0; j < H_SZ; j++) o = fmaf(fcw[lid*H_SZ + j], h[j], o);
        out[b*2 + lid] = o;
    }
}

// ============================================================
extern "C" void kernel_launch(void* const* d_in, const int* in_sizes, int n_in,
                              void* d_out, int out_size)
{
    const float* x     = (const float*)d_in[0];
    const float* ctw   = (const float*)d_in[1];
    const float* ctb   = (const float*)d_in[2];
    const float* csw   = (const float*)d_in[3];
    const float* gamma = (const float*)d_in[4];
    const float* beta  = (const float*)d_in[5];
    const float* mean  = (const float*)d_in[6];
    const float* var   = (const float*)d_in[7];
    const float* wih   = (const float*)d_in[8];
    const float* whh   = (const float*)d_in[9];
    const float* bih   = (const float*)d_in[10];
    const float* bhh   = (const float*)d_in[11];
    const float* fcw   = (const float*)d_in[12];
    const float* fcb   = (const float*)d_in[13];
    float* out = (float*)d_out;

    cudaFuncSetAttribute(conv_kernel, cudaFuncAttributeMaxDynamicSharedMemorySize, CONV_SMEM_BYTES);
    cudaFuncSetAttribute(lstm_kernel, cudaFuncAttributeMaxDynamicSharedMemorySize, LSTM_SMEM_BYTES);

    prep_kernel<<<G_SZ, 256>>>(ctw, ctb, csw, gamma, beta, mean, var, wih, bih, bhh);
    conv_kernel<<<dim3(3, B_SZ), CONV_THREADS, CONV_SMEM_BYTES>>>(x);
    lstm_kernel<<<B_SZ/LSTM_WARPS, 32*LSTM_WARPS, LSTM_SMEM_BYTES>>>(whh, fcw, fcb, out);
}